// round 13
// baseline (speedup 1.0000x reference)
#include <cuda_runtime.h>
#include <cuda_bf16.h>
#include <math.h>
#include <stdint.h>

#define T_TOK 8192
#define D_DIM 1024
#define H_DIM 4096
#define E_NUM 8
#define NSLOT (T_TOK * 2)

// ---------------------------------------------------------------------------
// Static device scratch
// ---------------------------------------------------------------------------
__device__ int   g_bad;               // 1 => FFMA fallback path
__device__ int   g_cnt[E_NUM];
__device__ int   g_off[E_NUM];
__device__ int   g_perm[E_NUM * T_TOK];
__device__ int   g_te[NSLOT];
__device__ int   g_tp[NSLOT];
__device__ float g_tw[NSLOT];
__device__ __align__(256) float g_h[(size_t)NSLOT * H_DIM];   // hidden fp32
__device__ __align__(256) float g_y[(size_t)NSLOT * D_DIM];   // per-slot out

// ---------------------------------------------------------------------------
#define MMA16816(c, a, b0, b1) \
    asm volatile("mma.sync.aligned.m16n8k16.row.col.f32.bf16.bf16.f32 " \
        "{%0,%1,%2,%3}, {%4,%5,%6,%7}, {%8,%9}, {%0,%1,%2,%3};" \
        : "+f"((c)[0]), "+f"((c)[1]), "+f"((c)[2]), "+f"((c)[3]) \
        : "r"((a)[0]), "r"((a)[1]), "r"((a)[2]), "r"((a)[3]), "r"(b0), "r"(b1))

__device__ __forceinline__ uint32_t pk2(__nv_bfloat16 a, __nv_bfloat16 b) {
    __nv_bfloat162 t; t.x = a; t.y = b;
    return *(uint32_t*)&t;
}

// ---------------------------------------------------------------------------
// K0: init counters + flag, then warp 1 probes mma.sync + fragment math
// (80B-stride probe kept; fragment index math is stride-independent).
// ---------------------------------------------------------------------------
__global__ void k_init_probe() {
    __shared__ char ps[80 * 16 + 80 * 8];
    int tid = threadIdx.x;
    if (tid < E_NUM) g_cnt[tid] = 0;
    if (tid == 0) g_bad = 0;
    __syncthreads();
    if (tid < 32 || tid >= 64) return;
    int lane = tid & 31;
    for (int i = lane; i < 16 * 32; i += 32) {
        int r = i >> 5, k = i & 31;
        *(__nv_bfloat16*)(ps + r * 80 + k * 2) =
            __float2bfloat16(0.0625f * (float)((r * 32 + k) % 23) - 0.6875f);
    }
    for (int i = lane; i < 8 * 32; i += 32) {
        int n = i >> 5, k = i & 31;
        *(__nv_bfloat16*)(ps + 1280 + n * 80 + k * 2) =
            __float2bfloat16(0.0625f * (float)((n * 32 + k * 3) % 19) - 0.5f);
    }
    __syncwarp();
    int l4 = lane >> 2, l2 = (lane & 3) * 4;
    float c[4] = {0.f, 0.f, 0.f, 0.f};
#pragma unroll
    for (int ks = 0; ks < 2; ks++) {
        int kb = ks * 32 + l2;
        uint32_t a[4], b0, b1;
        a[0] = *(const uint32_t*)(ps + l4 * 80 + kb);
        a[1] = *(const uint32_t*)(ps + (l4 + 8) * 80 + kb);
        a[2] = *(const uint32_t*)(ps + l4 * 80 + kb + 16);
        a[3] = *(const uint32_t*)(ps + (l4 + 8) * 80 + kb + 16);
        b0 = *(const uint32_t*)(ps + 1280 + l4 * 80 + kb);
        b1 = *(const uint32_t*)(ps + 1280 + l4 * 80 + kb + 16);
        MMA16816(c, a, b0, b1);
    }
#pragma unroll
    for (int q = 0; q < 4; q++) {
        int r  = (lane >> 2) + ((q >= 2) ? 8 : 0);
        int cc = (lane & 3) * 2 + (q & 1);
        float ref = 0.0f;
        for (int k = 0; k < 32; k++)
            ref += __bfloat162float(*(__nv_bfloat16*)(ps + r * 80 + k * 2)) *
                   __bfloat162float(*(__nv_bfloat16*)(ps + 1280 + cc * 80 + k * 2));
        if (fabsf(c[q] - ref) > 1e-2f) atomicExch(&g_bad, 1);
    }
}

// ---------------------------------------------------------------------------
// Gating (proven)
// ---------------------------------------------------------------------------
__global__ void k_gate(const float* __restrict__ x,
                       const float* __restrict__ gw,
                       const float* __restrict__ gb) {
    int warp = (blockIdx.x * blockDim.x + threadIdx.x) >> 5;
    int lane = threadIdx.x & 31;
    if (warp >= T_TOK) return;
    const float* xr = x + (size_t)warp * D_DIM;
    float acc[E_NUM];
#pragma unroll
    for (int e = 0; e < E_NUM; e++) acc[e] = 0.0f;
    for (int d = lane; d < D_DIM; d += 32) {
        float xv = xr[d];
        const float* g = gw + d * E_NUM;
#pragma unroll
        for (int e = 0; e < E_NUM; e++) acc[e] += xv * g[e];
    }
#pragma unroll
    for (int e = 0; e < E_NUM; e++)
#pragma unroll
        for (int o = 16; o > 0; o >>= 1)
            acc[e] += __shfl_xor_sync(0xFFFFFFFFu, acc[e], o);
    if (lane == 0) {
        float best = -1e30f, sec = -1e30f;
        int bi = 0, si = 0;
#pragma unroll
        for (int e = 0; e < E_NUM; e++) {
            float v = acc[e] + gb[e];
            if (v > best) { sec = best; si = bi; best = v; bi = e; }
            else if (v > sec) { sec = v; si = e; }
        }
        float g1 = 1.0f / (1.0f + expf(best - sec));
        float g0 = 1.0f - g1;
        int p0 = atomicAdd(&g_cnt[bi], 1);
        g_perm[bi * T_TOK + p0] = warp;
        g_te[2 * warp] = bi; g_tp[2 * warp] = p0; g_tw[2 * warp] = g0;
        int p1 = atomicAdd(&g_cnt[si], 1);
        g_perm[si * T_TOK + p1] = warp;
        g_te[2 * warp + 1] = si; g_tp[2 * warp + 1] = p1; g_tw[2 * warp + 1] = g1;
    }
}

__global__ void k_off() {
    if (threadIdx.x == 0) {
        int s = 0;
#pragma unroll
        for (int e = 0; e < E_NUM; e++) { g_off[e] = s; s += g_cnt[e]; }
    }
}

// ---------------------------------------------------------------------------
// MMA grouped GEMM, double-buffered, one barrier per chunk.
// BM=128, BN=128, BK=16; 256 thr; warp tile 64x32.
// Row stride 48B (32B data + 16B pad) -> fragment loads hit all 32 banks.
// Stage 24576B: AHI@0, ALO@6144, BHI@12288, BLO@18432. 2 stages = 49152B.
// ---------------------------------------------------------------------------
#define STG   24576
#define S_ALO 6144
#define S_BHI 12288
#define S_BLO 18432

template<int Nd, int Kd, bool IS1>
__global__ __launch_bounds__(256)
void k_gemm(const float* __restrict__ x,
            const float* __restrict__ w,
            const float* __restrict__ bias) {
    if (g_bad) return;
    int e = blockIdx.z;
    int cnt = g_cnt[e];
    int m0 = blockIdx.y * 128;
    if (m0 >= cnt) return;
    int n0 = blockIdx.x * 128;
    int off = g_off[e];

    __shared__ __align__(16) char sm[2 * STG];
    int tid = threadIdx.x, lane = tid & 31, wid = tid >> 5;
    int wm = wid >> 2, wn = wid & 3;

    // ---- A loader: row = tid/2, 8 floats per thread per chunk
    int ar = tid >> 1, axc = tid & 1;
    int mrow = m0 + ar; if (mrow > cnt - 1) mrow = cnt - 1;
    const float* aSrc;
    if (IS1) {
        int tok = g_perm[e * T_TOK + mrow];
        aSrc = x + (size_t)tok * Kd;
    } else {
        aSrc = g_h + (size_t)(off + mrow) * Kd;
    }
    aSrc += axc * 8;
    uint32_t aDst = (uint32_t)(ar * 48 + axc * 16);

    // ---- B loader: kp = lane&3 (+4q), n = wid*16 + lane>>2 (+8r)
    int bl4 = lane >> 2, bl3 = lane & 3;
    const float* bSrc = w + (size_t)e * Kd * Nd + (n0 + wid * 16 + bl4);
    uint32_t bDst = (uint32_t)(S_BHI + (wid * 16 + bl4) * 48 + bl3 * 4);

    uint2    aH2[2], aL2[2];
    uint32_t bH[4], bL[4];

#define FETCH(c) do { \
    _Pragma("unroll") \
    for (int j = 0; j < 2; j++) { \
        float4 f = *(const float4*)(aSrc + (size_t)(c) * 16 + j * 4); \
        __nv_bfloat16 hx = __float2bfloat16(f.x), hy = __float2bfloat16(f.y); \
        __nv_bfloat16 hz = __float2bfloat16(f.z), hw = __float2bfloat16(f.w); \
        aH2[j].x = pk2(hx, hy); aH2[j].y = pk2(hz, hw); \
        aL2[j].x = pk2(__float2bfloat16(f.x - __bfloat162float(hx)), \
                       __float2bfloat16(f.y - __bfloat162float(hy))); \
        aL2[j].y = pk2(__float2bfloat16(f.z - __bfloat162float(hz)), \
                       __float2bfloat16(f.w - __bfloat162float(hw))); \
    } \
    _Pragma("unroll") \
    for (int q = 0; q < 2; q++) { \
        _Pragma("unroll") \
        for (int r = 0; r < 2; r++) { \
            const float* p = bSrc + (size_t)((c) * 16 + 2 * bl3 + 8 * q) * Nd + 8 * r; \
            float f0 = p[0], f1 = p[Nd]; \
            __nv_bfloat16 h0 = __float2bfloat16(f0), h1 = __float2bfloat16(f1); \
            bH[q * 2 + r] = pk2(h0, h1); \
            bL[q * 2 + r] = pk2(__float2bfloat16(f0 - __bfloat162float(h0)), \
                                __float2bfloat16(f1 - __bfloat162float(h1))); \
        } \
    } } while (0)

#define STORE(buf) do { \
    char* s_ = sm + (buf) * STG; \
    _Pragma("unroll") \
    for (int j = 0; j < 2; j++) { \
        *(uint2*)(s_ + aDst + j * 8) = aH2[j]; \
        *(uint2*)(s_ + S_ALO + aDst + j * 8) = aL2[j]; \
    } \
    _Pragma("unroll") \
    for (int i = 0; i < 4; i++) { \
        uint32_t o_ = (uint32_t)((i >> 1) * 16 + (i & 1) * 384); \
        *(uint32_t*)(s_ + bDst + o_) = bH[i]; \
        *(uint32_t*)(s_ + bDst + (S_BLO - S_BHI) + o_) = bL[i]; \
    } } while (0)

    float acc[4][4][4];
#pragma unroll
    for (int i = 0; i < 4; i++)
#pragma unroll
        for (int j = 0; j < 4; j++)
#pragma unroll
            for (int q = 0; q < 4; q++) acc[i][j][q] = 0.0f;

    const int NC = Kd / 16;
    int l4 = lane >> 2;
    int kb = (lane & 3) * 4;

    FETCH(0); STORE(0); FETCH(1);
    __syncthreads();

    for (int c = 0; c < NC; c++) {
        char* base = sm + (c & 1) * STG;
        uint32_t af[4][4];
        // ---- ah passes: hh + hl
#pragma unroll
        for (int mt = 0; mt < 4; mt++) {
            int rb = (wm * 64 + mt * 16 + l4) * 48;
            af[mt][0] = *(const uint32_t*)(base + rb + kb);
            af[mt][1] = *(const uint32_t*)(base + rb + 384 + kb);
            af[mt][2] = *(const uint32_t*)(base + rb + kb + 16);
            af[mt][3] = *(const uint32_t*)(base + rb + 384 + kb + 16);
        }
#pragma unroll
        for (int o = 0; o < 4; o++) {
            int nb = (wn * 32 + o * 8 + l4) * 48;
            uint32_t bh0 = *(const uint32_t*)(base + S_BHI + nb + kb);
            uint32_t bh1 = *(const uint32_t*)(base + S_BHI + nb + kb + 16);
            uint32_t bl0 = *(const uint32_t*)(base + S_BLO + nb + kb);
            uint32_t bl1 = *(const uint32_t*)(base + S_BLO + nb + kb + 16);
#pragma unroll
            for (int mt = 0; mt < 4; mt++) MMA16816(acc[mt][o], af[mt], bh0, bh1);
#pragma unroll
            for (int mt = 0; mt < 4; mt++) MMA16816(acc[mt][o], af[mt], bl0, bl1);
        }
        // ---- al pass: lh
#pragma unroll
        for (int mt = 0; mt < 4; mt++) {
            int rb = (wm * 64 + mt * 16 + l4) * 48;
            af[mt][0] = *(const uint32_t*)(base + S_ALO + rb + kb);
            af[mt][1] = *(const uint32_t*)(base + S_ALO + rb + 384 + kb);
            af[mt][2] = *(const uint32_t*)(base + S_ALO + rb + kb + 16);
            af[mt][3] = *(const uint32_t*)(base + S_ALO + rb + 384 + kb + 16);
        }
#pragma unroll
        for (int o = 0; o < 4; o++) {
            int nb = (wn * 32 + o * 8 + l4) * 48;
            uint32_t bh0 = *(const uint32_t*)(base + S_BHI + nb + kb);
            uint32_t bh1 = *(const uint32_t*)(base + S_BHI + nb + kb + 16);
#pragma unroll
            for (int mt = 0; mt < 4; mt++) MMA16816(acc[mt][o], af[mt], bh0, bh1);
        }
        // ---- pipeline: store chunk c+1 (other buffer), fetch chunk c+2
        if (c + 1 < NC) STORE((c + 1) & 1);
        if (c + 2 < NC) FETCH(c + 2);
        __syncthreads();
    }

    // ---- epilogue
#pragma unroll
    for (int mt = 0; mt < 4; mt++) {
#pragma unroll
        for (int rr = 0; rr < 2; rr++) {
            int r = m0 + wm * 64 + mt * 16 + (lane >> 2) + rr * 8;
            if (r >= cnt) continue;
            if (IS1) {
                const float* be = bias + (size_t)e * Nd + n0;
                float* hr = g_h + (size_t)(off + r) * H_DIM + n0;
#pragma unroll
                for (int o = 0; o < 4; o++) {
                    int col = wn * 32 + o * 8 + (lane & 3) * 2;
                    float v0 = acc[mt][o][rr * 2 + 0] + be[col];
                    float v1 = acc[mt][o][rr * 2 + 1] + be[col + 1];
                    v0 = 0.5f * v0 * (1.0f + erff(v0 * 0.70710678118654752f));
                    v1 = 0.5f * v1 * (1.0f + erff(v1 * 0.70710678118654752f));
                    float2 v; v.x = v0; v.y = v1;
                    *(float2*)(hr + col) = v;
                }
            } else {
                float* yr = g_y + (size_t)(off + r) * D_DIM + n0;
#pragma unroll
                for (int o = 0; o < 4; o++) {
                    int col = wn * 32 + o * 8 + (lane & 3) * 2;
                    float2 v;
                    v.x = acc[mt][o][rr * 2 + 0];
                    v.y = acc[mt][o][rr * 2 + 1];
                    *(float2*)(yr + col) = v;
                }
            }
        }
    }
#undef FETCH
#undef STORE
}

// ---------------------------------------------------------------------------
// Combine (mma path)
// ---------------------------------------------------------------------------
__global__ void k_combine(const float* __restrict__ b2, float* __restrict__ out) {
    if (g_bad) return;
    int t = blockIdx.x;
    int d = threadIdx.x * 4;
    int e0 = g_te[2 * t], e1 = g_te[2 * t + 1];
    float w0 = g_tw[2 * t], w1 = g_tw[2 * t + 1];
    size_t s0 = (size_t)(g_off[e0] + g_tp[2 * t]) * D_DIM;
    size_t s1 = (size_t)(g_off[e1] + g_tp[2 * t + 1]) * D_DIM;
    float4 y0 = *(const float4*)(g_y + s0 + d);
    float4 y1 = *(const float4*)(g_y + s1 + d);
    float4 c0 = *(const float4*)(b2 + (size_t)e0 * D_DIM + d);
    float4 c1 = *(const float4*)(b2 + (size_t)e1 * D_DIM + d);
    float4 o;
    o.x = w0 * (y0.x + c0.x) + w1 * (y1.x + c1.x);
    o.y = w0 * (y0.y + c0.y) + w1 * (y1.y + c1.y);
    o.z = w0 * (y0.z + c0.z) + w1 * (y1.z + c1.z);
    o.w = w0 * (y0.w + c0.w) + w1 * (y1.w + c1.w);
    *(float4*)(out + (size_t)t * D_DIM + d) = o;
}

// ===========================================================================
// FALLBACK PATH (g_bad==1): FFMA pipeline, fp32 hidden in g_h
// ===========================================================================
__global__ void k_zero(float* __restrict__ out, int n) {
    if (!g_bad) return;
    int i = blockIdx.x * blockDim.x + threadIdx.x;
    int stride = gridDim.x * blockDim.x;
    for (; i < n; i += stride) out[i] = 0.0f;
}

__global__ __launch_bounds__(256)
void k_g1f(const float* __restrict__ x,
           const float* __restrict__ w1,
           const float* __restrict__ b1) {
    if (!g_bad) return;
    int e   = blockIdx.z;
    int cnt = g_cnt[e];
    int m0  = blockIdx.y * 128;
    if (m0 >= cnt) return;
    int n0  = blockIdx.x * 128;

    __shared__ float As[8][128];
    __shared__ float Bs[8][128];

    int tid = threadIdx.x;
    int am = tid >> 1;
    int ak = (tid & 1) * 4;
    int tok = -1;
    if (m0 + am < cnt) tok = g_perm[e * T_TOK + m0 + am];
    int bk = tid >> 5;
    int bn = (tid & 31) * 4;
    const float* w1e = w1 + (size_t)e * D_DIM * H_DIM;

    int tx = tid & 15, ty = tid >> 4;
    float acc[8][8];
#pragma unroll
    for (int i = 0; i < 8; i++)
#pragma unroll
        for (int j = 0; j < 8; j++) acc[i][j] = 0.0f;

    for (int k0 = 0; k0 < D_DIM; k0 += 8) {
        float4 av = make_float4(0.f, 0.f, 0.f, 0.f);
        if (tok >= 0) av = *(const float4*)(x + (size_t)tok * D_DIM + k0 + ak);
        float4 bv = *(const float4*)(w1e + (size_t)(k0 + bk) * H_DIM + n0 + bn);
        __syncthreads();
        As[ak + 0][am] = av.x; As[ak + 1][am] = av.y;
        As[ak + 2][am] = av.z; As[ak + 3][am] = av.w;
        *(float4*)&Bs[bk][bn] = bv;
        __syncthreads();
#pragma unroll
        for (int k = 0; k < 8; k++) {
            float a[8], b[8];
            *(float4*)(a)     = *(float4*)&As[k][ty * 4];
            *(float4*)(a + 4) = *(float4*)&As[k][64 + ty * 4];
            *(float4*)(b)     = *(float4*)&Bs[k][tx * 4];
            *(float4*)(b + 4) = *(float4*)&Bs[k][64 + tx * 4];
#pragma unroll
            for (int i = 0; i < 8; i++)
#pragma unroll
                for (int j = 0; j < 8; j++) acc[i][j] += a[i] * b[j];
        }
    }

    int off = g_off[e];
    const float* b1e = b1 + (size_t)e * H_DIM;
#pragma unroll
    for (int i = 0; i < 8; i++) {
        int rm = (i < 4) ? (ty * 4 + i) : (64 + ty * 4 + (i - 4));
        int m = m0 + rm;
        if (m >= cnt) continue;
        float* hrow = g_h + (size_t)(off + m) * H_DIM;
#pragma unroll
        for (int j = 0; j < 8; j++) {
            int rn = (j < 4) ? (tx * 4 + j) : (64 + tx * 4 + (j - 4));
            int n = n0 + rn;
            float h = acc[i][j] + b1e[n];
            h = 0.5f * h * (1.0f + erff(h * 0.70710678118654752f));
            hrow[n] = h;
        }
    }
}

__global__ __launch_bounds__(256)
void k_g2f(const float* __restrict__ w2,
           const float* __restrict__ b2,
           float* __restrict__ out) {
    if (!g_bad) return;
    int e   = blockIdx.z;
    int cnt = g_cnt[e];
    int m0  = blockIdx.y * 128;
    if (m0 >= cnt) return;
    int n0  = blockIdx.x * 128;
    int off = g_off[e];

    __shared__ float As[8][128];
    __shared__ float Bs[8][128];

    int tid = threadIdx.x;
    int am = tid >> 1;
    int ak = (tid & 1) * 4;
    bool avalid = (m0 + am < cnt);
    const float* arow = g_h + (size_t)(off + m0 + (avalid ? am : 0)) * H_DIM;
    int bk = tid >> 5;
    int bn = (tid & 31) * 4;
    const float* w2e = w2 + (size_t)e * H_DIM * D_DIM;

    int tx = tid & 15, ty = tid >> 4;
    float acc[8][8];
#pragma unroll
    for (int i = 0; i < 8; i++)
#pragma unroll
        for (int j = 0; j < 8; j++) acc[i][j] = 0.0f;

    for (int k0 = 0; k0 < H_DIM; k0 += 8) {
        float4 av = make_float4(0.f, 0.f, 0.f, 0.f);
        if (avalid) av = *(const float4*)(arow + k0 + ak);
        float4 bv = *(const float4*)(w2e + (size_t)(k0 + bk) * D_DIM + n0 + bn);
        __syncthreads();
        As[ak + 0][am] = av.x; As[ak + 1][am] = av.y;
        As[ak + 2][am] = av.z; As[ak + 3][am] = av.w;
        *(float4*)&Bs[bk][bn] = bv;
        __syncthreads();
#pragma unroll
        for (int k = 0; k < 8; k++) {
            float a[8], b[8];
            *(float4*)(a)     = *(float4*)&As[k][ty * 4];
            *(float4*)(a + 4) = *(float4*)&As[k][64 + ty * 4];
            *(float4*)(b)     = *(float4*)&Bs[k][tx * 4];
            *(float4*)(b + 4) = *(float4*)&Bs[k][64 + tx * 4];
#pragma unroll
            for (int i = 0; i < 8; i++)
#pragma unroll
                for (int j = 0; j < 8; j++) acc[i][j] += a[i] * b[j];
        }
    }

    const float* b2e = b2 + (size_t)e * D_DIM;
#pragma unroll
    for (int i = 0; i < 8; i++) {
        int rm = (i < 4) ? (ty * 4 + i) : (64 + ty * 4 + (i - 4));
        int m = m0 + rm;
        if (m >= cnt) continue;
        int   tok = g_perm[e * T_TOK + m];
        float w0 = g_tw[2 * tok], w1v = g_tw[2 * tok + 1];
        float w = (g_te[2 * tok] == e) ? w0 : w1v;
        float* orow = out + (size_t)tok * D_DIM;
#pragma unroll
        for (int j = 0; j < 8; j++) {
            int rn = (j < 4) ? (tx * 4 + j) : (64 + tx * 4 + (j - 4));
            int n = n0 + rn;
            float y = acc[i][j] + b2e[n];
            atomicAdd(&orow[n], w * y);
        }
    }
}

// ---------------------------------------------------------------------------
// Launch (k_gemm1 at app-launch index 3 — where ncu keeps landing)
// ---------------------------------------------------------------------------
extern "C" void kernel_launch(void* const* d_in, const int* in_sizes, int n_in,
                              void* d_out, int out_size) {
    const float* x  = (const float*)d_in[0];
    const float* gw = (const float*)d_in[1];
    const float* gb = (const float*)d_in[2];
    const float* w1 = (const float*)d_in[3];
    const float* b1 = (const float*)d_in[4];
    const float* w2 = (const float*)d_in[5];
    const float* b2 = (const float*)d_in[6];
    float* out = (float*)d_out;
    (void)in_sizes; (void)n_in;

    k_init_probe<<<1, 64>>>();                                         // 0
    k_gate<<<(T_TOK * 32 + 255) / 256, 256>>>(x, gw, gb);              // 1
    k_off<<<1, 32>>>();                                                // 2
    k_gemm<H_DIM, D_DIM, true>                                         // 3 <- ncu
        <<<dim3(H_DIM / 128, T_TOK / 128, E_NUM), 256>>>(x, w1, b1);
    k_gemm<D_DIM, H_DIM, false>                                        // 4
        <<<dim3(D_DIM / 128, T_TOK / 128, E_NUM), 256>>>(x, w2, b2);
    k_combine<<<T_TOK, 256>>>(b2, out);                                // 5
    k_zero<<<2048, 256>>>(out, out_size);                              // 6
    k_g1f<<<dim3(H_DIM / 128, T_TOK / 128, E_NUM), 256>>>(x, w1, b1);  // 7
    k_g2f<<<dim3(D_DIM / 128, T_TOK / 128, E_NUM), 256>>>(w2, b2, out);// 8
}

// round 14
// speedup vs baseline: 1.3840x; 1.3840x over previous
#include <cuda_runtime.h>
#include <cuda_bf16.h>
#include <math.h>
#include <stdint.h>

#define T_TOK 8192
#define D_DIM 1024
#define H_DIM 4096
#define E_NUM 8
#define NSLOT (T_TOK * 2)

// ---------------------------------------------------------------------------
// Static device scratch
// ---------------------------------------------------------------------------
__device__ int   g_bad;               // 1 => FFMA fallback path
__device__ int   g_cnt[E_NUM];
__device__ int   g_off[E_NUM];
__device__ int   g_perm[E_NUM * T_TOK];
__device__ int   g_te[NSLOT];
__device__ int   g_tp[NSLOT];
__device__ float g_tw[NSLOT];
__device__ __align__(256) float g_h[(size_t)NSLOT * H_DIM];   // hidden fp32
__device__ __align__(256) float g_y[(size_t)NSLOT * D_DIM];   // per-slot out

// ---------------------------------------------------------------------------
#define MMA16816(c, a, b0, b1) \
    asm volatile("mma.sync.aligned.m16n8k16.row.col.f32.bf16.bf16.f32 " \
        "{%0,%1,%2,%3}, {%4,%5,%6,%7}, {%8,%9}, {%0,%1,%2,%3};" \
        : "+f"((c)[0]), "+f"((c)[1]), "+f"((c)[2]), "+f"((c)[3]) \
        : "r"((a)[0]), "r"((a)[1]), "r"((a)[2]), "r"((a)[3]), "r"(b0), "r"(b1))

__device__ __forceinline__ uint32_t pk2(__nv_bfloat16 a, __nv_bfloat16 b) {
    __nv_bfloat162 t; t.x = a; t.y = b;
    return *(uint32_t*)&t;
}

// ---------------------------------------------------------------------------
// K0: init counters + flag; warp 1 probes mma.sync + fragment math.
// ---------------------------------------------------------------------------
__global__ void k_init_probe() {
    __shared__ char ps[80 * 16 + 80 * 8];
    int tid = threadIdx.x;
    if (tid < E_NUM) g_cnt[tid] = 0;
    if (tid == 0) g_bad = 0;
    __syncthreads();
    if (tid < 32 || tid >= 64) return;
    int lane = tid & 31;
    for (int i = lane; i < 16 * 32; i += 32) {
        int r = i >> 5, k = i & 31;
        *(__nv_bfloat16*)(ps + r * 80 + k * 2) =
            __float2bfloat16(0.0625f * (float)((r * 32 + k) % 23) - 0.6875f);
    }
    for (int i = lane; i < 8 * 32; i += 32) {
        int n = i >> 5, k = i & 31;
        *(__nv_bfloat16*)(ps + 1280 + n * 80 + k * 2) =
            __float2bfloat16(0.0625f * (float)((n * 32 + k * 3) % 19) - 0.5f);
    }
    __syncwarp();
    int l4 = lane >> 2, l2 = (lane & 3) * 4;
    float c[4] = {0.f, 0.f, 0.f, 0.f};
#pragma unroll
    for (int ks = 0; ks < 2; ks++) {
        int kb = ks * 32 + l2;
        uint32_t a[4], b0, b1;
        a[0] = *(const uint32_t*)(ps + l4 * 80 + kb);
        a[1] = *(const uint32_t*)(ps + (l4 + 8) * 80 + kb);
        a[2] = *(const uint32_t*)(ps + l4 * 80 + kb + 16);
        a[3] = *(const uint32_t*)(ps + (l4 + 8) * 80 + kb + 16);
        b0 = *(const uint32_t*)(ps + 1280 + l4 * 80 + kb);
        b1 = *(const uint32_t*)(ps + 1280 + l4 * 80 + kb + 16);
        MMA16816(c, a, b0, b1);
    }
#pragma unroll
    for (int q = 0; q < 4; q++) {
        int r  = (lane >> 2) + ((q >= 2) ? 8 : 0);
        int cc = (lane & 3) * 2 + (q & 1);
        float ref = 0.0f;
        for (int k = 0; k < 32; k++)
            ref += __bfloat162float(*(__nv_bfloat16*)(ps + r * 80 + k * 2)) *
                   __bfloat162float(*(__nv_bfloat16*)(ps + 1280 + cc * 80 + k * 2));
        if (fabsf(c[q] - ref) > 1e-2f) atomicExch(&g_bad, 1);
    }
}

// ---------------------------------------------------------------------------
// Gating (proven)
// ---------------------------------------------------------------------------
__global__ void k_gate(const float* __restrict__ x,
                       const float* __restrict__ gw,
                       const float* __restrict__ gb) {
    int warp = (blockIdx.x * blockDim.x + threadIdx.x) >> 5;
    int lane = threadIdx.x & 31;
    if (warp >= T_TOK) return;
    const float* xr = x + (size_t)warp * D_DIM;
    float acc[E_NUM];
#pragma unroll
    for (int e = 0; e < E_NUM; e++) acc[e] = 0.0f;
    for (int d = lane; d < D_DIM; d += 32) {
        float xv = xr[d];
        const float* g = gw + d * E_NUM;
#pragma unroll
        for (int e = 0; e < E_NUM; e++) acc[e] += xv * g[e];
    }
#pragma unroll
    for (int e = 0; e < E_NUM; e++)
#pragma unroll
        for (int o = 16; o > 0; o >>= 1)
            acc[e] += __shfl_xor_sync(0xFFFFFFFFu, acc[e], o);
    if (lane == 0) {
        float best = -1e30f, sec = -1e30f;
        int bi = 0, si = 0;
#pragma unroll
        for (int e = 0; e < E_NUM; e++) {
            float v = acc[e] + gb[e];
            if (v > best) { sec = best; si = bi; best = v; bi = e; }
            else if (v > sec) { sec = v; si = e; }
        }
        float g1 = 1.0f / (1.0f + expf(best - sec));
        float g0 = 1.0f - g1;
        int p0 = atomicAdd(&g_cnt[bi], 1);
        g_perm[bi * T_TOK + p0] = warp;
        g_te[2 * warp] = bi; g_tp[2 * warp] = p0; g_tw[2 * warp] = g0;
        int p1 = atomicAdd(&g_cnt[si], 1);
        g_perm[si * T_TOK + p1] = warp;
        g_te[2 * warp + 1] = si; g_tp[2 * warp + 1] = p1; g_tw[2 * warp + 1] = g1;
    }
}

__global__ void k_off() {
    if (threadIdx.x == 0) {
        int s = 0;
#pragma unroll
        for (int e = 0; e < E_NUM; e++) { g_off[e] = s; s += g_cnt[e]; }
    }
}

// ---------------------------------------------------------------------------
// MMA grouped GEMM (R9 core: single buffer, BK=32, 80B strides) with
// __launch_bounds__(256, 2) -> <=128 regs -> 2 CTAs/SM.
// smem rows stride 80B: AHI@0, ALO@10240, BHI@20480, BLO@30720. 40KB total.
// ---------------------------------------------------------------------------
#define S_AHI 0
#define S_ALO 10240
#define S_BHI 20480
#define S_BLO 30720

template<int Nd, int Kd, bool IS1>
__global__ __launch_bounds__(256, 2)
void k_gemm(const float* __restrict__ x,
            const float* __restrict__ w,
            const float* __restrict__ bias) {
    if (g_bad) return;
    int e = blockIdx.z;
    int cnt = g_cnt[e];
    int m0 = blockIdx.y * 128;
    if (m0 >= cnt) return;
    int n0 = blockIdx.x * 128;
    int off = g_off[e];

    __shared__ __align__(16) char sm[40960];
    int tid = threadIdx.x, lane = tid & 31, wid = tid >> 5;
    int wm = wid >> 2, wn = wid & 3;

    // ---- A loader: row = tid/2, half-row (16 floats) per thread
    int ar = tid >> 1, axc = tid & 1;
    int mrow = m0 + ar; if (mrow > cnt - 1) mrow = cnt - 1;
    const float* aSrc;
    if (IS1) {
        int tok = g_perm[e * T_TOK + mrow];
        aSrc = x + (size_t)tok * Kd;
    } else {
        aSrc = g_h + (size_t)(off + mrow) * Kd;
    }
    aSrc += axc * 16;
    uint32_t aDst = (uint32_t)(ar * 80 + axc * 32);

    // ---- B loader: lane-mapped for conflict-free STS.32
    int bl4 = lane >> 2, bl3 = lane & 3;
    const float* bSrc = w + (size_t)e * Kd * Nd + (n0 + wid * 16 + bl4);
    uint32_t bDst = (uint32_t)(S_BHI + (wid * 16 + bl4) * 80 + bl3 * 4);

    uint2    aH2[4], aL2[4];
    uint32_t bH[8], bL[8];

#define FETCH(c) do { \
    _Pragma("unroll") \
    for (int j = 0; j < 4; j++) { \
        float4 f = *(const float4*)(aSrc + (size_t)(c) * 32 + j * 4); \
        __nv_bfloat16 hx = __float2bfloat16(f.x), hy = __float2bfloat16(f.y); \
        __nv_bfloat16 hz = __float2bfloat16(f.z), hw = __float2bfloat16(f.w); \
        aH2[j].x = pk2(hx, hy); aH2[j].y = pk2(hz, hw); \
        aL2[j].x = pk2(__float2bfloat16(f.x - __bfloat162float(hx)), \
                       __float2bfloat16(f.y - __bfloat162float(hy))); \
        aL2[j].y = pk2(__float2bfloat16(f.z - __bfloat162float(hz)), \
                       __float2bfloat16(f.w - __bfloat162float(hw))); \
    } \
    _Pragma("unroll") \
    for (int q = 0; q < 4; q++) { \
        _Pragma("unroll") \
        for (int r = 0; r < 2; r++) { \
            const float* p = bSrc + (size_t)((c) * 32 + 2 * bl3 + 8 * q) * Nd + 8 * r; \
            float f0 = p[0], f1 = p[Nd]; \
            __nv_bfloat16 h0 = __float2bfloat16(f0), h1 = __float2bfloat16(f1); \
            bH[q * 2 + r] = pk2(h0, h1); \
            bL[q * 2 + r] = pk2(__float2bfloat16(f0 - __bfloat162float(h0)), \
                                __float2bfloat16(f1 - __bfloat162float(h1))); \
        } \
    } } while (0)

#define STORE() do { \
    _Pragma("unroll") \
    for (int j = 0; j < 4; j++) { \
        *(uint2*)(sm + S_AHI + aDst + j * 8) = aH2[j]; \
        *(uint2*)(sm + S_ALO + aDst + j * 8) = aL2[j]; \
    } \
    _Pragma("unroll") \
    for (int i = 0; i < 8; i++) { \
        uint32_t o_ = (uint32_t)((i >> 1) * 16 + (i & 1) * 640); \
        *(uint32_t*)(sm + bDst + o_) = bH[i]; \
        *(uint32_t*)(sm + bDst + (S_BLO - S_BHI) + o_) = bL[i]; \
    } } while (0)

    float acc[4][4][4];
#pragma unroll
    for (int i = 0; i < 4; i++)
#pragma unroll
        for (int j = 0; j < 4; j++)
#pragma unroll
            for (int q = 0; q < 4; q++) acc[i][j][q] = 0.0f;

    const int NC = Kd / 32;
    int l4 = lane >> 2;
    int l2 = (lane & 3) * 4;

    FETCH(0);
    for (int c = 0; c < NC; c++) {
        __syncthreads();
        STORE();
        __syncthreads();
        if (c + 1 < NC) FETCH(c + 1);

#pragma unroll
        for (int ks = 0; ks < 2; ks++) {
            int kb = ks * 32 + l2;
            uint32_t af[4][4];
            // -------- ah passes: hh + hl
#pragma unroll
            for (int mt = 0; mt < 4; mt++) {
                int rb = (wm * 64 + mt * 16 + l4) * 80;
                af[mt][0] = *(const uint32_t*)(sm + S_AHI + rb + kb);
                af[mt][1] = *(const uint32_t*)(sm + S_AHI + rb + 640 + kb);
                af[mt][2] = *(const uint32_t*)(sm + S_AHI + rb + kb + 16);
                af[mt][3] = *(const uint32_t*)(sm + S_AHI + rb + 640 + kb + 16);
            }
#pragma unroll
            for (int o = 0; o < 4; o++) {
                int nb = (wn * 32 + o * 8 + l4) * 80;
                uint32_t bh0 = *(const uint32_t*)(sm + S_BHI + nb + kb);
                uint32_t bh1 = *(const uint32_t*)(sm + S_BHI + nb + kb + 16);
                uint32_t bl0 = *(const uint32_t*)(sm + S_BLO + nb + kb);
                uint32_t bl1 = *(const uint32_t*)(sm + S_BLO + nb + kb + 16);
#pragma unroll
                for (int mt = 0; mt < 4; mt++) MMA16816(acc[mt][o], af[mt], bh0, bh1);
#pragma unroll
                for (int mt = 0; mt < 4; mt++) MMA16816(acc[mt][o], af[mt], bl0, bl1);
            }
            // -------- al pass: lh (reuse af registers)
#pragma unroll
            for (int mt = 0; mt < 4; mt++) {
                int rb = (wm * 64 + mt * 16 + l4) * 80;
                af[mt][0] = *(const uint32_t*)(sm + S_ALO + rb + kb);
                af[mt][1] = *(const uint32_t*)(sm + S_ALO + rb + 640 + kb);
                af[mt][2] = *(const uint32_t*)(sm + S_ALO + rb + kb + 16);
                af[mt][3] = *(const uint32_t*)(sm + S_ALO + rb + 640 + kb + 16);
            }
#pragma unroll
            for (int o = 0; o < 4; o++) {
                int nb = (wn * 32 + o * 8 + l4) * 80;
                uint32_t bh0 = *(const uint32_t*)(sm + S_BHI + nb + kb);
                uint32_t bh1 = *(const uint32_t*)(sm + S_BHI + nb + kb + 16);
#pragma unroll
                for (int mt = 0; mt < 4; mt++) MMA16816(acc[mt][o], af[mt], bh0, bh1);
            }
        }
    }

    // ---- epilogue
#pragma unroll
    for (int mt = 0; mt < 4; mt++) {
#pragma unroll
        for (int rr = 0; rr < 2; rr++) {
            int r = m0 + wm * 64 + mt * 16 + (lane >> 2) + rr * 8;
            if (r >= cnt) continue;
            if (IS1) {
                const float* be = bias + (size_t)e * Nd + n0;
                float* hr = g_h + (size_t)(off + r) * H_DIM + n0;
#pragma unroll
                for (int o = 0; o < 4; o++) {
                    int col = wn * 32 + o * 8 + (lane & 3) * 2;
                    float v0 = acc[mt][o][rr * 2 + 0] + be[col];
                    float v1 = acc[mt][o][rr * 2 + 1] + be[col + 1];
                    v0 = 0.5f * v0 * (1.0f + erff(v0 * 0.70710678118654752f));
                    v1 = 0.5f * v1 * (1.0f + erff(v1 * 0.70710678118654752f));
                    float2 v; v.x = v0; v.y = v1;
                    *(float2*)(hr + col) = v;
                }
            } else {
                float* yr = g_y + (size_t)(off + r) * D_DIM + n0;
#pragma unroll
                for (int o = 0; o < 4; o++) {
                    int col = wn * 32 + o * 8 + (lane & 3) * 2;
                    float2 v;
                    v.x = acc[mt][o][rr * 2 + 0];
                    v.y = acc[mt][o][rr * 2 + 1];
                    *(float2*)(yr + col) = v;
                }
            }
        }
    }
#undef FETCH
#undef STORE
}

// ---------------------------------------------------------------------------
// Combine (mma path)
// ---------------------------------------------------------------------------
__global__ void k_combine(const float* __restrict__ b2, float* __restrict__ out) {
    if (g_bad) return;
    int t = blockIdx.x;
    int d = threadIdx.x * 4;
    int e0 = g_te[2 * t], e1 = g_te[2 * t + 1];
    float w0 = g_tw[2 * t], w1 = g_tw[2 * t + 1];
    size_t s0 = (size_t)(g_off[e0] + g_tp[2 * t]) * D_DIM;
    size_t s1 = (size_t)(g_off[e1] + g_tp[2 * t + 1]) * D_DIM;
    float4 y0 = *(const float4*)(g_y + s0 + d);
    float4 y1 = *(const float4*)(g_y + s1 + d);
    float4 c0 = *(const float4*)(b2 + (size_t)e0 * D_DIM + d);
    float4 c1 = *(const float4*)(b2 + (size_t)e1 * D_DIM + d);
    float4 o;
    o.x = w0 * (y0.x + c0.x) + w1 * (y1.x + c1.x);
    o.y = w0 * (y0.y + c0.y) + w1 * (y1.y + c1.y);
    o.z = w0 * (y0.z + c0.z) + w1 * (y1.z + c1.z);
    o.w = w0 * (y0.w + c0.w) + w1 * (y1.w + c1.w);
    *(float4*)(out + (size_t)t * D_DIM + d) = o;
}

// ===========================================================================
// FALLBACK PATH (g_bad==1): FFMA pipeline, fp32 hidden in g_h
// ===========================================================================
__global__ void k_zero(float* __restrict__ out, int n) {
    if (!g_bad) return;
    int i = blockIdx.x * blockDim.x + threadIdx.x;
    int stride = gridDim.x * blockDim.x;
    for (; i < n; i += stride) out[i] = 0.0f;
}

__global__ __launch_bounds__(256)
void k_g1f(const float* __restrict__ x,
           const float* __restrict__ w1,
           const float* __restrict__ b1) {
    if (!g_bad) return;
    int e   = blockIdx.z;
    int cnt = g_cnt[e];
    int m0  = blockIdx.y * 128;
    if (m0 >= cnt) return;
    int n0  = blockIdx.x * 128;

    __shared__ float As[8][128];
    __shared__ float Bs[8][128];

    int tid = threadIdx.x;
    int am = tid >> 1;
    int ak = (tid & 1) * 4;
    int tok = -1;
    if (m0 + am < cnt) tok = g_perm[e * T_TOK + m0 + am];
    int bk = tid >> 5;
    int bn = (tid & 31) * 4;
    const float* w1e = w1 + (size_t)e * D_DIM * H_DIM;

    int tx = tid & 15, ty = tid >> 4;
    float acc[8][8];
#pragma unroll
    for (int i = 0; i < 8; i++)
#pragma unroll
        for (int j = 0; j < 8; j++) acc[i][j] = 0.0f;

    for (int k0 = 0; k0 < D_DIM; k0 += 8) {
        float4 av = make_float4(0.f, 0.f, 0.f, 0.f);
        if (tok >= 0) av = *(const float4*)(x + (size_t)tok * D_DIM + k0 + ak);
        float4 bv = *(const float4*)(w1e + (size_t)(k0 + bk) * H_DIM + n0 + bn);
        __syncthreads();
        As[ak + 0][am] = av.x; As[ak + 1][am] = av.y;
        As[ak + 2][am] = av.z; As[ak + 3][am] = av.w;
        *(float4*)&Bs[bk][bn] = bv;
        __syncthreads();
#pragma unroll
        for (int k = 0; k < 8; k++) {
            float a[8], b[8];
            *(float4*)(a)     = *(float4*)&As[k][ty * 4];
            *(float4*)(a + 4) = *(float4*)&As[k][64 + ty * 4];
            *(float4*)(b)     = *(float4*)&Bs[k][tx * 4];
            *(float4*)(b + 4) = *(float4*)&Bs[k][64 + tx * 4];
#pragma unroll
            for (int i = 0; i < 8; i++)
#pragma unroll
                for (int j = 0; j < 8; j++) acc[i][j] += a[i] * b[j];
        }
    }

    int off = g_off[e];
    const float* b1e = b1 + (size_t)e * H_DIM;
#pragma unroll
    for (int i = 0; i < 8; i++) {
        int rm = (i < 4) ? (ty * 4 + i) : (64 + ty * 4 + (i - 4));
        int m = m0 + rm;
        if (m >= cnt) continue;
        float* hrow = g_h + (size_t)(off + m) * H_DIM;
#pragma unroll
        for (int j = 0; j < 8; j++) {
            int rn = (j < 4) ? (tx * 4 + j) : (64 + tx * 4 + (j - 4));
            int n = n0 + rn;
            float h = acc[i][j] + b1e[n];
            h = 0.5f * h * (1.0f + erff(h * 0.70710678118654752f));
            hrow[n] = h;
        }
    }
}

__global__ __launch_bounds__(256)
void k_g2f(const float* __restrict__ w2,
           const float* __restrict__ b2,
           float* __restrict__ out) {
    if (!g_bad) return;
    int e   = blockIdx.z;
    int cnt = g_cnt[e];
    int m0  = blockIdx.y * 128;
    if (m0 >= cnt) return;
    int n0  = blockIdx.x * 128;
    int off = g_off[e];

    __shared__ float As[8][128];
    __shared__ float Bs[8][128];

    int tid = threadIdx.x;
    int am = tid >> 1;
    int ak = (tid & 1) * 4;
    bool avalid = (m0 + am < cnt);
    const float* arow = g_h + (size_t)(off + m0 + (avalid ? am : 0)) * H_DIM;
    int bk = tid >> 5;
    int bn = (tid & 31) * 4;
    const float* w2e = w2 + (size_t)e * H_DIM * D_DIM;

    int tx = tid & 15, ty = tid >> 4;
    float acc[8][8];
#pragma unroll
    for (int i = 0; i < 8; i++)
#pragma unroll
        for (int j = 0; j < 8; j++) acc[i][j] = 0.0f;

    for (int k0 = 0; k0 < H_DIM; k0 += 8) {
        float4 av = make_float4(0.f, 0.f, 0.f, 0.f);
        if (avalid) av = *(const float4*)(arow + k0 + ak);
        float4 bv = *(const float4*)(w2e + (size_t)(k0 + bk) * D_DIM + n0 + bn);
        __syncthreads();
        As[ak + 0][am] = av.x; As[ak + 1][am] = av.y;
        As[ak + 2][am] = av.z; As[ak + 3][am] = av.w;
        *(float4*)&Bs[bk][bn] = bv;
        __syncthreads();
#pragma unroll
        for (int k = 0; k < 8; k++) {
            float a[8], b[8];
            *(float4*)(a)     = *(float4*)&As[k][ty * 4];
            *(float4*)(a + 4) = *(float4*)&As[k][64 + ty * 4];
            *(float4*)(b)     = *(float4*)&Bs[k][tx * 4];
            *(float4*)(b + 4) = *(float4*)&Bs[k][64 + tx * 4];
#pragma unroll
            for (int i = 0; i < 8; i++)
#pragma unroll
                for (int j = 0; j < 8; j++) acc[i][j] += a[i] * b[j];
        }
    }

    const float* b2e = b2 + (size_t)e * D_DIM;
#pragma unroll
    for (int i = 0; i < 8; i++) {
        int rm = (i < 4) ? (ty * 4 + i) : (64 + ty * 4 + (i - 4));
        int m = m0 + rm;
        if (m >= cnt) continue;
        int   tok = g_perm[e * T_TOK + m];
        float w0 = g_tw[2 * tok], w1v = g_tw[2 * tok + 1];
        float w = (g_te[2 * tok] == e) ? w0 : w1v;
        float* orow = out + (size_t)tok * D_DIM;
#pragma unroll
        for (int j = 0; j < 8; j++) {
            int rn = (j < 4) ? (tx * 4 + j) : (64 + tx * 4 + (j - 4));
            int n = n0 + rn;
            float y = acc[i][j] + b2e[n];
            atomicAdd(&orow[n], w * y);
        }
    }
}

// ---------------------------------------------------------------------------
// Launch (k_gemm1 at app-launch index 3 — where ncu lands)
// ---------------------------------------------------------------------------
extern "C" void kernel_launch(void* const* d_in, const int* in_sizes, int n_in,
                              void* d_out, int out_size) {
    const float* x  = (const float*)d_in[0];
    const float* gw = (const float*)d_in[1];
    const float* gb = (const float*)d_in[2];
    const float* w1 = (const float*)d_in[3];
    const float* b1 = (const float*)d_in[4];
    const float* w2 = (const float*)d_in[5];
    const float* b2 = (const float*)d_in[6];
    float* out = (float*)d_out;
    (void)in_sizes; (void)n_in;

    k_init_probe<<<1, 64>>>();                                         // 0
    k_gate<<<(T_TOK * 32 + 255) / 256, 256>>>(x, gw, gb);              // 1
    k_off<<<1, 32>>>();                                                // 2
    k_gemm<H_DIM, D_DIM, true>                                         // 3 <- ncu
        <<<dim3(H_DIM / 128, T_TOK / 128, E_NUM), 256>>>(x, w1, b1);
    k_gemm<D_DIM, H_DIM, false>                                        // 4
        <<<dim3(D_DIM / 128, T_TOK / 128, E_NUM), 256>>>(x, w2, b2);
    k_combine<<<T_TOK, 256>>>(b2, out);                                // 5
    k_zero<<<2048, 256>>>(out, out_size);                              // 6
    k_g1f<<<dim3(H_DIM / 128, T_TOK / 128, E_NUM), 256>>>(x, w1, b1);  // 7
    k_g2f<<<dim3(D_DIM / 128, T_TOK / 128, E_NUM), 256>>>(w2, b2, out);// 8
}

// round 15
// speedup vs baseline: 1.4649x; 1.0584x over previous
#include <cuda_runtime.h>
#include <cuda_bf16.h>
#include <math.h>
#include <stdint.h>

#define T_TOK 8192
#define D_DIM 1024
#define H_DIM 4096
#define E_NUM 8
#define NSLOT (T_TOK * 2)

// ---------------------------------------------------------------------------
// Static device scratch
// ---------------------------------------------------------------------------
__device__ int   g_bad;               // 1 => FFMA fallback path
__device__ int   g_cnt[E_NUM];
__device__ int   g_off[E_NUM];
__device__ int   g_perm[E_NUM * T_TOK];
__device__ int   g_te[NSLOT];
__device__ int   g_tp[NSLOT];
__device__ float g_tw[NSLOT];
__device__ __align__(256) float g_h[(size_t)NSLOT * H_DIM];   // hidden fp32
__device__ __align__(256) float g_y[(size_t)NSLOT * D_DIM];   // per-slot out

// ---------------------------------------------------------------------------
#define MMA16816(c, a, b0, b1) \
    asm volatile("mma.sync.aligned.m16n8k16.row.col.f32.bf16.bf16.f32 " \
        "{%0,%1,%2,%3}, {%4,%5,%6,%7}, {%8,%9}, {%0,%1,%2,%3};" \
        : "+f"((c)[0]), "+f"((c)[1]), "+f"((c)[2]), "+f"((c)[3]) \
        : "r"((a)[0]), "r"((a)[1]), "r"((a)[2]), "r"((a)[3]), "r"(b0), "r"(b1))

__device__ __forceinline__ uint32_t pk2(__nv_bfloat16 a, __nv_bfloat16 b) {
    __nv_bfloat162 t; t.x = a; t.y = b;
    return *(uint32_t*)&t;
}

// ---------------------------------------------------------------------------
// K0: init counters + flag; warp 1 probes mma.sync + fragment math.
// ---------------------------------------------------------------------------
__global__ void k_init_probe() {
    __shared__ char ps[80 * 16 + 80 * 8];
    int tid = threadIdx.x;
    if (tid < E_NUM) g_cnt[tid] = 0;
    if (tid == 0) g_bad = 0;
    __syncthreads();
    if (tid < 32 || tid >= 64) return;
    int lane = tid & 31;
    for (int i = lane; i < 16 * 32; i += 32) {
        int r = i >> 5, k = i & 31;
        *(__nv_bfloat16*)(ps + r * 80 + k * 2) =
            __float2bfloat16(0.0625f * (float)((r * 32 + k) % 23) - 0.6875f);
    }
    for (int i = lane; i < 8 * 32; i += 32) {
        int n = i >> 5, k = i & 31;
        *(__nv_bfloat16*)(ps + 1280 + n * 80 + k * 2) =
            __float2bfloat16(0.0625f * (float)((n * 32 + k * 3) % 19) - 0.5f);
    }
    __syncwarp();
    int l4 = lane >> 2, l2 = (lane & 3) * 4;
    float c[4] = {0.f, 0.f, 0.f, 0.f};
#pragma unroll
    for (int ks = 0; ks < 2; ks++) {
        int kb = ks * 32 + l2;
        uint32_t a[4], b0, b1;
        a[0] = *(const uint32_t*)(ps + l4 * 80 + kb);
        a[1] = *(const uint32_t*)(ps + (l4 + 8) * 80 + kb);
        a[2] = *(const uint32_t*)(ps + l4 * 80 + kb + 16);
        a[3] = *(const uint32_t*)(ps + (l4 + 8) * 80 + kb + 16);
        b0 = *(const uint32_t*)(ps + 1280 + l4 * 80 + kb);
        b1 = *(const uint32_t*)(ps + 1280 + l4 * 80 + kb + 16);
        MMA16816(c, a, b0, b1);
    }
#pragma unroll
    for (int q = 0; q < 4; q++) {
        int r  = (lane >> 2) + ((q >= 2) ? 8 : 0);
        int cc = (lane & 3) * 2 + (q & 1);
        float ref = 0.0f;
        for (int k = 0; k < 32; k++)
            ref += __bfloat162float(*(__nv_bfloat16*)(ps + r * 80 + k * 2)) *
                   __bfloat162float(*(__nv_bfloat16*)(ps + 1280 + cc * 80 + k * 2));
        if (fabsf(c[q] - ref) > 1e-2f) atomicExch(&g_bad, 1);
    }
}

// ---------------------------------------------------------------------------
// Gating (proven)
// ---------------------------------------------------------------------------
__global__ void k_gate(const float* __restrict__ x,
                       const float* __restrict__ gw,
                       const float* __restrict__ gb) {
    int warp = (blockIdx.x * blockDim.x + threadIdx.x) >> 5;
    int lane = threadIdx.x & 31;
    if (warp >= T_TOK) return;
    const float* xr = x + (size_t)warp * D_DIM;
    float acc[E_NUM];
#pragma unroll
    for (int e = 0; e < E_NUM; e++) acc[e] = 0.0f;
    for (int d = lane; d < D_DIM; d += 32) {
        float xv = xr[d];
        const float* g = gw + d * E_NUM;
#pragma unroll
        for (int e = 0; e < E_NUM; e++) acc[e] += xv * g[e];
    }
#pragma unroll
    for (int e = 0; e < E_NUM; e++)
#pragma unroll
        for (int o = 16; o > 0; o >>= 1)
            acc[e] += __shfl_xor_sync(0xFFFFFFFFu, acc[e], o);
    if (lane == 0) {
        float best = -1e30f, sec = -1e30f;
        int bi = 0, si = 0;
#pragma unroll
        for (int e = 0; e < E_NUM; e++) {
            float v = acc[e] + gb[e];
            if (v > best) { sec = best; si = bi; best = v; bi = e; }
            else if (v > sec) { sec = v; si = e; }
        }
        float g1 = 1.0f / (1.0f + expf(best - sec));
        float g0 = 1.0f - g1;
        int p0 = atomicAdd(&g_cnt[bi], 1);
        g_perm[bi * T_TOK + p0] = warp;
        g_te[2 * warp] = bi; g_tp[2 * warp] = p0; g_tw[2 * warp] = g0;
        int p1 = atomicAdd(&g_cnt[si], 1);
        g_perm[si * T_TOK + p1] = warp;
        g_te[2 * warp + 1] = si; g_tp[2 * warp + 1] = p1; g_tw[2 * warp + 1] = g1;
    }
}

__global__ void k_off() {
    if (threadIdx.x == 0) {
        int s = 0;
#pragma unroll
        for (int e = 0; e < E_NUM; e++) { g_off[e] = s; s += g_cnt[e]; }
    }
}

// ---------------------------------------------------------------------------
// smem layout (per 40KB stage): AHI@0, ALO@10240, BHI@20480, BLO@30720.
// Rows stride 80B. Fragment math identical to R14 (probe-validated).
// ---------------------------------------------------------------------------
#define S_AHI 0
#define S_ALO 10240
#define S_BHI 20480
#define S_BLO 30720
#define STG_B 40960

// Shared loader/compute bodies via macros parameterized on smem base.
#define GFETCH(c) do { \
    _Pragma("unroll") \
    for (int j = 0; j < 4; j++) { \
        float4 f = *(const float4*)(aSrc + (size_t)(c) * 32 + j * 4); \
        __nv_bfloat16 hx = __float2bfloat16(f.x), hy = __float2bfloat16(f.y); \
        __nv_bfloat16 hz = __float2bfloat16(f.z), hw = __float2bfloat16(f.w); \
        aH2[j].x = pk2(hx, hy); aH2[j].y = pk2(hz, hw); \
        aL2[j].x = pk2(__float2bfloat16(f.x - __bfloat162float(hx)), \
                       __float2bfloat16(f.y - __bfloat162float(hy))); \
        aL2[j].y = pk2(__float2bfloat16(f.z - __bfloat162float(hz)), \
                       __float2bfloat16(f.w - __bfloat162float(hw))); \
    } \
    _Pragma("unroll") \
    for (int q = 0; q < 4; q++) { \
        _Pragma("unroll") \
        for (int r = 0; r < 2; r++) { \
            const float* p = bSrc + (size_t)((c) * 32 + 2 * bl3 + 8 * q) * Nd + 8 * r; \
            float f0 = p[0], f1 = p[Nd]; \
            __nv_bfloat16 h0 = __float2bfloat16(f0), h1 = __float2bfloat16(f1); \
            bH[q * 2 + r] = pk2(h0, h1); \
            bL[q * 2 + r] = pk2(__float2bfloat16(f0 - __bfloat162float(h0)), \
                                __float2bfloat16(f1 - __bfloat162float(h1))); \
        } \
    } } while (0)

#define GSTORE(sbase) do { \
    char* s_ = (sbase); \
    _Pragma("unroll") \
    for (int j = 0; j < 4; j++) { \
        *(uint2*)(s_ + S_AHI + aDst + j * 8) = aH2[j]; \
        *(uint2*)(s_ + S_ALO + aDst + j * 8) = aL2[j]; \
    } \
    _Pragma("unroll") \
    for (int i = 0; i < 8; i++) { \
        uint32_t o_ = (uint32_t)((i >> 1) * 16 + (i & 1) * 640); \
        *(uint32_t*)(s_ + bDst + o_) = bH[i]; \
        *(uint32_t*)(s_ + bDst + (S_BLO - S_BHI) + o_) = bL[i]; \
    } } while (0)

#define GCOMPUTE(sbase) do { \
    char* base = (sbase); \
    _Pragma("unroll") \
    for (int ks = 0; ks < 2; ks++) { \
        int kb = ks * 32 + l2; \
        uint32_t af[4][4]; \
        _Pragma("unroll") \
        for (int mt = 0; mt < 4; mt++) { \
            int rb = (wm * 64 + mt * 16 + l4) * 80; \
            af[mt][0] = *(const uint32_t*)(base + S_AHI + rb + kb); \
            af[mt][1] = *(const uint32_t*)(base + S_AHI + rb + 640 + kb); \
            af[mt][2] = *(const uint32_t*)(base + S_AHI + rb + kb + 16); \
            af[mt][3] = *(const uint32_t*)(base + S_AHI + rb + 640 + kb + 16); \
        } \
        _Pragma("unroll") \
        for (int o = 0; o < 4; o++) { \
            int nb = (wn * 32 + o * 8 + l4) * 80; \
            uint32_t bh0 = *(const uint32_t*)(base + S_BHI + nb + kb); \
            uint32_t bh1 = *(const uint32_t*)(base + S_BHI + nb + kb + 16); \
            uint32_t bl0 = *(const uint32_t*)(base + S_BLO + nb + kb); \
            uint32_t bl1 = *(const uint32_t*)(base + S_BLO + nb + kb + 16); \
            _Pragma("unroll") \
            for (int mt = 0; mt < 4; mt++) MMA16816(acc[mt][o], af[mt], bh0, bh1); \
            _Pragma("unroll") \
            for (int mt = 0; mt < 4; mt++) MMA16816(acc[mt][o], af[mt], bl0, bl1); \
        } \
        _Pragma("unroll") \
        for (int mt = 0; mt < 4; mt++) { \
            int rb = (wm * 64 + mt * 16 + l4) * 80; \
            af[mt][0] = *(const uint32_t*)(base + S_ALO + rb + kb); \
            af[mt][1] = *(const uint32_t*)(base + S_ALO + rb + 640 + kb); \
            af[mt][2] = *(const uint32_t*)(base + S_ALO + rb + kb + 16); \
            af[mt][3] = *(const uint32_t*)(base + S_ALO + rb + 640 + kb + 16); \
        } \
        _Pragma("unroll") \
        for (int o = 0; o < 4; o++) { \
            int nb = (wn * 32 + o * 8 + l4) * 80; \
            uint32_t bh0 = *(const uint32_t*)(base + S_BHI + nb + kb); \
            uint32_t bh1 = *(const uint32_t*)(base + S_BHI + nb + kb + 16); \
            _Pragma("unroll") \
            for (int mt = 0; mt < 4; mt++) MMA16816(acc[mt][o], af[mt], bh0, bh1); \
        } \
    } } while (0)

#define GEPILOGUE() do { \
    _Pragma("unroll") \
    for (int mt = 0; mt < 4; mt++) { \
        _Pragma("unroll") \
        for (int rr = 0; rr < 2; rr++) { \
            int r = m0 + wm * 64 + mt * 16 + (lane >> 2) + rr * 8; \
            if (r >= cnt) continue; \
            if (IS1) { \
                const float* be = bias + (size_t)e * Nd + n0; \
                float* hr = g_h + (size_t)(off + r) * H_DIM + n0; \
                _Pragma("unroll") \
                for (int o = 0; o < 4; o++) { \
                    int col = wn * 32 + o * 8 + (lane & 3) * 2; \
                    float v0 = acc[mt][o][rr * 2 + 0] + be[col]; \
                    float v1 = acc[mt][o][rr * 2 + 1] + be[col + 1]; \
                    v0 = 0.5f * v0 * (1.0f + erff(v0 * 0.70710678118654752f)); \
                    v1 = 0.5f * v1 * (1.0f + erff(v1 * 0.70710678118654752f)); \
                    float2 v; v.x = v0; v.y = v1; \
                    *(float2*)(hr + col) = v; \
                } \
            } else { \
                float* yr = g_y + (size_t)(off + r) * D_DIM + n0; \
                _Pragma("unroll") \
                for (int o = 0; o < 4; o++) { \
                    int col = wn * 32 + o * 8 + (lane & 3) * 2; \
                    float2 v; \
                    v.x = acc[mt][o][rr * 2 + 0]; \
                    v.y = acc[mt][o][rr * 2 + 1]; \
                    *(float2*)(yr + col) = v; \
                } \
            } \
        } \
    } } while (0)

#define GPROLOG() \
    int e = blockIdx.z; \
    int cnt = g_cnt[e]; \
    int m0 = blockIdx.y * 128; \
    if (m0 >= cnt) return; \
    int n0 = blockIdx.x * 128; \
    int off = g_off[e]; \
    int tid = threadIdx.x, lane = tid & 31, wid = tid >> 5; \
    int wm = wid >> 2, wn = wid & 3; \
    int ar = tid >> 1, axc = tid & 1; \
    int mrow = m0 + ar; if (mrow > cnt - 1) mrow = cnt - 1; \
    const float* aSrc; \
    if (IS1) { \
        int tok = g_perm[e * T_TOK + mrow]; \
        aSrc = x + (size_t)tok * Kd; \
    } else { \
        aSrc = g_h + (size_t)(off + mrow) * Kd; \
    } \
    aSrc += axc * 16; \
    uint32_t aDst = (uint32_t)(ar * 80 + axc * 32); \
    int bl4 = lane >> 2, bl3 = lane & 3; \
    (void)bl4; \
    const float* bSrc = w + (size_t)e * Kd * Nd + (n0 + wid * 16 + (lane >> 2)); \
    uint32_t bDst = (uint32_t)(S_BHI + (wid * 16 + (lane >> 2)) * 80 + bl3 * 4); \
    uint2    aH2[4], aL2[4]; \
    uint32_t bH[8], bL[8]; \
    float acc[4][4][4]; \
    _Pragma("unroll") \
    for (int i = 0; i < 4; i++) \
        _Pragma("unroll") \
        for (int j = 0; j < 4; j++) \
            _Pragma("unroll") \
            for (int q = 0; q < 4; q++) acc[i][j][q] = 0.0f; \
    const int NC = Kd / 32; \
    int l4 = lane >> 2; \
    int l2 = (lane & 3) * 4;

// ---------------------------------------------------------------------------
// Variant A (preferred): double-buffered, 80KB dynamic smem, 1 sync/chunk.
// ---------------------------------------------------------------------------
template<int Nd, int Kd, bool IS1>
__global__ __launch_bounds__(256, 2)
void k_gemm_b(const float* __restrict__ x,
              const float* __restrict__ w,
              const float* __restrict__ bias) {
    if (g_bad) return;
    extern __shared__ __align__(16) char smx[];
    GPROLOG();

    GFETCH(0);
    GSTORE(smx);            // stage 0 -> buf 0
    if (NC > 1) GFETCH(1);
    __syncthreads();

    for (int c = 0; c < NC; c++) {
        if (c + 1 < NC) GSTORE(smx + ((c + 1) & 1) * STG_B);  // other buffer
        if (c + 2 < NC) GFETCH(c + 2);
        GCOMPUTE(smx + (c & 1) * STG_B);
        __syncthreads();
    }
    GEPILOGUE();
}

// ---------------------------------------------------------------------------
// Variant B (fallback if big-smem opt-in fails): R14 single-buffer, static.
// ---------------------------------------------------------------------------
template<int Nd, int Kd, bool IS1>
__global__ __launch_bounds__(256, 2)
void k_gemm_s(const float* __restrict__ x,
              const float* __restrict__ w,
              const float* __restrict__ bias) {
    if (g_bad) return;
    __shared__ __align__(16) char sms[40960];
    GPROLOG();

    GFETCH(0);
    for (int c = 0; c < NC; c++) {
        __syncthreads();
        GSTORE(sms);
        __syncthreads();
        if (c + 1 < NC) GFETCH(c + 1);
        GCOMPUTE(sms);
    }
    GEPILOGUE();
}

// ---------------------------------------------------------------------------
// Combine (mma path)
// ---------------------------------------------------------------------------
__global__ void k_combine(const float* __restrict__ b2, float* __restrict__ out) {
    if (g_bad) return;
    int t = blockIdx.x;
    int d = threadIdx.x * 4;
    int e0 = g_te[2 * t], e1 = g_te[2 * t + 1];
    float w0 = g_tw[2 * t], w1 = g_tw[2 * t + 1];
    size_t s0 = (size_t)(g_off[e0] + g_tp[2 * t]) * D_DIM;
    size_t s1 = (size_t)(g_off[e1] + g_tp[2 * t + 1]) * D_DIM;
    float4 y0 = *(const float4*)(g_y + s0 + d);
    float4 y1 = *(const float4*)(g_y + s1 + d);
    float4 c0 = *(const float4*)(b2 + (size_t)e0 * D_DIM + d);
    float4 c1 = *(const float4*)(b2 + (size_t)e1 * D_DIM + d);
    float4 o;
    o.x = w0 * (y0.x + c0.x) + w1 * (y1.x + c1.x);
    o.y = w0 * (y0.y + c0.y) + w1 * (y1.y + c1.y);
    o.z = w0 * (y0.z + c0.z) + w1 * (y1.z + c1.z);
    o.w = w0 * (y0.w + c0.w) + w1 * (y1.w + c1.w);
    *(float4*)(out + (size_t)t * D_DIM + d) = o;
}

// ===========================================================================
// FALLBACK PATH (g_bad==1): FFMA pipeline, fp32 hidden in g_h
// ===========================================================================
__global__ void k_zero(float* __restrict__ out, int n) {
    if (!g_bad) return;
    int i = blockIdx.x * blockDim.x + threadIdx.x;
    int stride = gridDim.x * blockDim.x;
    for (; i < n; i += stride) out[i] = 0.0f;
}

__global__ __launch_bounds__(256)
void k_g1f(const float* __restrict__ x,
           const float* __restrict__ w1,
           const float* __restrict__ b1) {
    if (!g_bad) return;
    int e   = blockIdx.z;
    int cnt = g_cnt[e];
    int m0  = blockIdx.y * 128;
    if (m0 >= cnt) return;
    int n0  = blockIdx.x * 128;

    __shared__ float As[8][128];
    __shared__ float Bs[8][128];

    int tid = threadIdx.x;
    int am = tid >> 1;
    int ak = (tid & 1) * 4;
    int tok = -1;
    if (m0 + am < cnt) tok = g_perm[e * T_TOK + m0 + am];
    int bk = tid >> 5;
    int bn = (tid & 31) * 4;
    const float* w1e = w1 + (size_t)e * D_DIM * H_DIM;

    int tx = tid & 15, ty = tid >> 4;
    float acc[8][8];
#pragma unroll
    for (int i = 0; i < 8; i++)
#pragma unroll
        for (int j = 0; j < 8; j++) acc[i][j] = 0.0f;

    for (int k0 = 0; k0 < D_DIM; k0 += 8) {
        float4 av = make_float4(0.f, 0.f, 0.f, 0.f);
        if (tok >= 0) av = *(const float4*)(x + (size_t)tok * D_DIM + k0 + ak);
        float4 bv = *(const float4*)(w1e + (size_t)(k0 + bk) * H_DIM + n0 + bn);
        __syncthreads();
        As[ak + 0][am] = av.x; As[ak + 1][am] = av.y;
        As[ak + 2][am] = av.z; As[ak + 3][am] = av.w;
        *(float4*)&Bs[bk][bn] = bv;
        __syncthreads();
#pragma unroll
        for (int k = 0; k < 8; k++) {
            float a[8], b[8];
            *(float4*)(a)     = *(float4*)&As[k][ty * 4];
            *(float4*)(a + 4) = *(float4*)&As[k][64 + ty * 4];
            *(float4*)(b)     = *(float4*)&Bs[k][tx * 4];
            *(float4*)(b + 4) = *(float4*)&Bs[k][64 + tx * 4];
#pragma unroll
            for (int i = 0; i < 8; i++)
#pragma unroll
                for (int j = 0; j < 8; j++) acc[i][j] += a[i] * b[j];
        }
    }

    int off = g_off[e];
    const float* b1e = b1 + (size_t)e * H_DIM;
#pragma unroll
    for (int i = 0; i < 8; i++) {
        int rm = (i < 4) ? (ty * 4 + i) : (64 + ty * 4 + (i - 4));
        int m = m0 + rm;
        if (m >= cnt) continue;
        float* hrow = g_h + (size_t)(off + m) * H_DIM;
#pragma unroll
        for (int j = 0; j < 8; j++) {
            int rn = (j < 4) ? (tx * 4 + j) : (64 + tx * 4 + (j - 4));
            int n = n0 + rn;
            float h = acc[i][j] + b1e[n];
            h = 0.5f * h * (1.0f + erff(h * 0.70710678118654752f));
            hrow[n] = h;
        }
    }
}

__global__ __launch_bounds__(256)
void k_g2f(const float* __restrict__ w2,
           const float* __restrict__ b2,
           float* __restrict__ out) {
    if (!g_bad) return;
    int e   = blockIdx.z;
    int cnt = g_cnt[e];
    int m0  = blockIdx.y * 128;
    if (m0 >= cnt) return;
    int n0  = blockIdx.x * 128;
    int off = g_off[e];

    __shared__ float As[8][128];
    __shared__ float Bs[8][128];

    int tid = threadIdx.x;
    int am = tid >> 1;
    int ak = (tid & 1) * 4;
    bool avalid = (m0 + am < cnt);
    const float* arow = g_h + (size_t)(off + m0 + (avalid ? am : 0)) * H_DIM;
    int bk = tid >> 5;
    int bn = (tid & 31) * 4;
    const float* w2e = w2 + (size_t)e * H_DIM * D_DIM;

    int tx = tid & 15, ty = tid >> 4;
    float acc[8][8];
#pragma unroll
    for (int i = 0; i < 8; i++)
#pragma unroll
        for (int j = 0; j < 8; j++) acc[i][j] = 0.0f;

    for (int k0 = 0; k0 < H_DIM; k0 += 8) {
        float4 av = make_float4(0.f, 0.f, 0.f, 0.f);
        if (avalid) av = *(const float4*)(arow + k0 + ak);
        float4 bv = *(const float4*)(w2e + (size_t)(k0 + bk) * D_DIM + n0 + bn);
        __syncthreads();
        As[ak + 0][am] = av.x; As[ak + 1][am] = av.y;
        As[ak + 2][am] = av.z; As[ak + 3][am] = av.w;
        *(float4*)&Bs[bk][bn] = bv;
        __syncthreads();
#pragma unroll
        for (int k = 0; k < 8; k++) {
            float a[8], b[8];
            *(float4*)(a)     = *(float4*)&As[k][ty * 4];
            *(float4*)(a + 4) = *(float4*)&As[k][64 + ty * 4];
            *(float4*)(b)     = *(float4*)&Bs[k][tx * 4];
            *(float4*)(b + 4) = *(float4*)&Bs[k][64 + tx * 4];
#pragma unroll
            for (int i = 0; i < 8; i++)
#pragma unroll
                for (int j = 0; j < 8; j++) acc[i][j] += a[i] * b[j];
        }
    }

    const float* b2e = b2 + (size_t)e * D_DIM;
#pragma unroll
    for (int i = 0; i < 8; i++) {
        int rm = (i < 4) ? (ty * 4 + i) : (64 + ty * 4 + (i - 4));
        int m = m0 + rm;
        if (m >= cnt) continue;
        int   tok = g_perm[e * T_TOK + m];
        float w0 = g_tw[2 * tok], w1v = g_tw[2 * tok + 1];
        float w = (g_te[2 * tok] == e) ? w0 : w1v;
        float* orow = out + (size_t)tok * D_DIM;
#pragma unroll
        for (int j = 0; j < 8; j++) {
            int rn = (j < 4) ? (tx * 4 + j) : (64 + tx * 4 + (j - 4));
            int n = n0 + rn;
            float y = acc[i][j] + b2e[n];
            atomicAdd(&orow[n], w * y);
        }
    }
}

// ---------------------------------------------------------------------------
// Launch (k_gemm1 stays at app-launch index 3 for ncu)
// ---------------------------------------------------------------------------
extern "C" void kernel_launch(void* const* d_in, const int* in_sizes, int n_in,
                              void* d_out, int out_size) {
    const float* x  = (const float*)d_in[0];
    const float* gw = (const float*)d_in[1];
    const float* gb = (const float*)d_in[2];
    const float* w1 = (const float*)d_in[3];
    const float* b1 = (const float*)d_in[4];
    const float* w2 = (const float*)d_in[5];
    const float* b2 = (const float*)d_in[6];
    float* out = (float*)d_out;
    (void)in_sizes; (void)n_in;

    // Opt-in to 80KB dynamic smem; on ANY failure use the proven R14 variant.
    cudaError_t ea = cudaFuncSetAttribute(k_gemm_b<H_DIM, D_DIM, true>,
                        cudaFuncAttributeMaxDynamicSharedMemorySize, 2 * STG_B);
    cudaError_t eb = cudaFuncSetAttribute(k_gemm_b<D_DIM, H_DIM, false>,
                        cudaFuncAttributeMaxDynamicSharedMemorySize, 2 * STG_B);
    bool big = (ea == cudaSuccess) && (eb == cudaSuccess);

    k_init_probe<<<1, 64>>>();                                         // 0
    k_gate<<<(T_TOK * 32 + 255) / 256, 256>>>(x, gw, gb);              // 1
    k_off<<<1, 32>>>();                                                // 2
    if (big) {
        k_gemm_b<H_DIM, D_DIM, true>                                   // 3 <- ncu
            <<<dim3(H_DIM / 128, T_TOK / 128, E_NUM), 256, 2 * STG_B>>>(x, w1, b1);
        k_gemm_b<D_DIM, H_DIM, false>                                  // 4
            <<<dim3(D_DIM / 128, T_TOK / 128, E_NUM), 256, 2 * STG_B>>>(x, w2, b2);
    } else {
        k_gemm_s<H_DIM, D_DIM, true>
            <<<dim3(H_DIM / 128, T_TOK / 128, E_NUM), 256>>>(x, w1, b1);
        k_gemm_s<D_DIM, H_DIM, false>
            <<<dim3(D_DIM / 128, T_TOK / 128, E_NUM), 256>>>(x, w2, b2);
    }
    k_combine<<<T_TOK, 256>>>(b2, out);                                // 5
    k_zero<<<2048, 256>>>(out, out_size);                              // 6
    k_g1f<<<dim3(H_DIM / 128, T_TOK / 128, E_NUM), 256>>>(x, w1, b1);  // 7
    k_g2f<<<dim3(D_DIM / 128, T_TOK / 128, E_NUM), 256>>>(w2, b2, out);// 8
}